// round 16
// baseline (speedup 1.0000x reference)
#include <cuda_runtime.h>
#include <cuda_fp16.h>
#include <cstdint>

// ShapeConv single fused kernel: fp16 mma.sync (f16 accum) argmax-selection
// phase, grid-wide ticket barrier (all 296 blocks resident: 148 SMs x 2), then
// exact fp32 recompute phase distributed over all warps. Selection mainloop is
// at the measured legacy-HMMA rate floor (~12.5 cyc/SMSP/instr); this round
// removes the separate tail kernel (+launch) that cost ~7us.

#define BB 32
#define CC 3
#define LL 8192
#define OO 128
#define KW 64
#define WW (LL - KW + 1)   /* 8129 valid windows */
#define KRED 192
#define APW 100            /* A pitch in 32-bit words (96 data + 4 pad) */
#define NBLK 296           /* 2 CTAs/SM x 148 SMs: all resident, barrier-safe */
#define NWRP (NBLK * 8)
#define WT_TOTAL (BB * 4 * 128)   /* 16384 warp-tiles: 32o x 64t */

#define A_OFF 0u           /* 128*APW f16x2 words = 51200 B */
#define P_OFF 51200u       /* 8 warps x 128 f32 prefix arrays */
#define SMEM_BYTES 55296

typedef unsigned long long ull;

__device__ ull g_max2[BB * OO];          // (mono(val)<<32 | t), zero-init
__device__ unsigned int g_counter;       // phase-1 arrival ticket
__device__ unsigned int g_done;          // phase-2 completion ticket

__device__ __forceinline__ unsigned int f2mono(float f) {
    unsigned int u = __float_as_uint(f);
    return (u & 0x80000000u) ? ~u : (u | 0x80000000u);
}
__device__ __forceinline__ uint32_t pack_h2(float lo, float hi) {
    __half2 h = __floats2half2_rn(lo, hi);
    return *(uint32_t*)&h;
}
__device__ __forceinline__ void mma_f16a(uint32_t* d, const uint32_t* a,
                                         uint32_t b0, uint32_t b1) {
    asm volatile(
        "mma.sync.aligned.m16n8k16.row.col.f16.f16.f16.f16 "
        "{%0,%1}, {%2,%3,%4,%5}, {%6,%7}, {%0,%1};"
        : "+r"(d[0]), "+r"(d[1])
        : "r"(a[0]), "r"(a[1]), "r"(a[2]), "r"(a[3]), "r"(b0), "r"(b1));
}
__device__ __forceinline__ void ldsm_x4(uint32_t* a, uint32_t saddr) {
    asm volatile(
        "ldmatrix.sync.aligned.m8n8.x4.shared.b16 {%0,%1,%2,%3}, [%4];"
        : "=r"(a[0]), "=r"(a[1]), "=r"(a[2]), "=r"(a[3]) : "r"(saddr));
}

// ---------------- one warp-tile: 32 o x 64 t, K=192 ----------------
template <bool EDGE>
__device__ __forceinline__ void process_tile(
    const float* __restrict__ xb, int t0, uint32_t addrA0, uint32_t addrA1,
    float* __restrict__ Pw, int b, int os, int lane, int r4, int q4)
{
    __syncwarp();   // previous tile's Pw reads complete

    // ---- exclusive prefix of squared sums over [t0, t0+128) ----
    {
        int gi = t0 + 4 * lane;
        if (EDGE) gi = min(gi, LL - 4);
        float4 c0 = *(const float4*)(xb + gi);
        float4 c1 = *(const float4*)(xb + LL + gi);
        float4 c2 = *(const float4*)(xb + 2 * LL + gi);
        float s0 = c0.x*c0.x + c1.x*c1.x + c2.x*c2.x;
        float s1 = c0.y*c0.y + c1.y*c1.y + c2.y*c2.y;
        float s2 = c0.z*c0.z + c1.z*c1.z + c2.z*c2.z;
        float s3 = c0.w*c0.w + c1.w*c1.w + c2.w*c2.w;
        float e1 = s0, e2 = s0 + s1, e3 = e2 + s2, tot = e3 + s3;
        float sc = tot;
        #pragma unroll
        for (int d = 1; d < 32; d <<= 1) {
            float t = __shfl_up_sync(0xffffffffu, sc, d);
            if (lane >= d) sc += t;
        }
        float base = sc - tot;
        *(float4*)(Pw + 4*lane) = make_float4(base, base+e1, base+e2, base+e3);
    }
    __syncwarp();

    // ---- fp16 MMA mainloop (f16 accum), B frags straight from global ----
    uint32_t acc[2][8][2];
    #pragma unroll
    for (int mi = 0; mi < 2; ++mi)
        #pragma unroll
        for (int nf = 0; nf < 8; ++nf) { acc[mi][nf][0] = 0u; acc[mi][nf][1] = 0u; }

    const int off = t0 + r4 + 2 * q4;
    #pragma unroll
    for (int c = 0; c < CC; ++c) {
        const float* xc = xb + c * LL;
        uint32_t bb[15];
        #pragma unroll
        for (int u = 0; u < 15; ++u) {
            float v0, v1;
            if (EDGE) {
                int p = off + 8 * u;
                v0 = xc[min(p, LL - 1)];
                v1 = xc[min(p + 1, LL - 1)];
            } else {
                v0 = xc[off + 8 * u];
                v1 = xc[off + 8 * u + 1];
            }
            bb[u] = pack_h2(v0, v1);
        }
        #pragma unroll
        for (int j = 0; j < 4; ++j) {
            const uint32_t cb = (uint32_t)(c * 32 + j * 8) << 2;
            uint32_t a[2][4];
            ldsm_x4(a[0], addrA0 + cb);
            ldsm_x4(a[1], addrA1 + cb);
            #pragma unroll
            for (int nf = 0; nf < 8; ++nf) {
                uint32_t b0 = bb[2 * j + nf], b1 = bb[2 * j + nf + 1];
                mma_f16a(acc[0][nf], a[0], b0, b1);
                mma_f16a(acc[1][nf], a[1], b0, b1);
            }
        }
    }

    // ---- epilogue: (val, t) argmax per row with exact-win subtraction ----
    float mv[2][2];  int mx[2][2];
    #pragma unroll
    for (int mi = 0; mi < 2; ++mi)
        #pragma unroll
        for (int h = 0; h < 2; ++h) { mv[mi][h] = __int_as_float(0xff800000); mx[mi][h] = t0; }

    #pragma unroll
    for (int nf = 0; nf < 8; ++nf) {
        const int n0 = nf * 8 + 2 * q4;
        float w0 = 0.5f * (Pw[n0 + 64] - Pw[n0]);
        float w1 = 0.5f * (Pw[n0 + 65] - Pw[n0 + 1]);
        if (EDGE) {
            if (t0 + n0 >= WW)     w0 = __int_as_float(0x7f800000);
            if (t0 + n0 + 1 >= WW) w1 = __int_as_float(0x7f800000);
        }
        const int ti0 = t0 + n0, ti1 = t0 + n0 + 1;
        #pragma unroll
        for (int mi = 0; mi < 2; ++mi) {
            float2 lo = __half22float2(*(__half2*)&acc[mi][nf][0]);
            float2 hi = __half22float2(*(__half2*)&acc[mi][nf][1]);
            float f0 = lo.x - w0, f1 = lo.y - w1;
            float f2 = hi.x - w0, f3 = hi.y - w1;
            if (f0 > mv[mi][0]) { mv[mi][0] = f0; mx[mi][0] = ti0; }
            if (f1 > mv[mi][0]) { mv[mi][0] = f1; mx[mi][0] = ti1; }
            if (f2 > mv[mi][1]) { mv[mi][1] = f2; mx[mi][1] = ti0; }
            if (f3 > mv[mi][1]) { mv[mi][1] = f3; mx[mi][1] = ti1; }
        }
    }
    #pragma unroll
    for (int mi = 0; mi < 2; ++mi)
        #pragma unroll
        for (int h = 0; h < 2; ++h) {
            #pragma unroll
            for (int d = 1; d <= 2; d <<= 1) {
                float ov = __shfl_xor_sync(0xffffffffu, mv[mi][h], d);
                int   oi = __shfl_xor_sync(0xffffffffu, mx[mi][h], d);
                if (ov > mv[mi][h]) { mv[mi][h] = ov; mx[mi][h] = oi; }
            }
        }
    if (q4 == 0) {
        #pragma unroll
        for (int mi = 0; mi < 2; ++mi)
            #pragma unroll
            for (int h = 0; h < 2; ++h) {
                int row = os * 32 + mi * 16 + h * 8 + r4;
                ull pk = ((ull)f2mono(mv[mi][h]) << 32) | (unsigned)mx[mi][h];
                atomicMax(&g_max2[b * OO + row], pk);
            }
    }
}

extern "C" __global__ void __launch_bounds__(256, 2)
shapeconv_fused(const float* __restrict__ xg, const float* __restrict__ wg,
                float* __restrict__ out) {
    extern __shared__ char smem[];
    uint32_t* A_s = (uint32_t*)(smem + A_OFF);   // [128][APW] f16x2

    const int tid  = threadIdx.x;
    const int wid  = tid >> 5;
    const int lane = tid & 31;
    const int r4   = lane >> 2;
    const int q4   = lane & 3;

    float* Pw = (float*)(smem + P_OFF) + wid * 128;

    // ---- A staging: warp w owns o-rows [16w,16w+16); coalesced float2 -> f16x2
    {
        const int o0w = wid * 16;
        #pragma unroll 4
        for (int oi = 0; oi < 16; ++oi) {
            const int o = o0w + oi;
            const float2* wp = (const float2*)(wg + o * KRED);
            float2 v0 = wp[lane], v1 = wp[lane + 32], v2 = wp[lane + 64];
            uint32_t* ap = A_s + o * APW;
            ap[lane]      = pack_h2(v0.x, v0.y);
            ap[lane + 32] = pack_h2(v1.x, v1.y);
            ap[lane + 64] = pack_h2(v2.x, v2.y);
        }
    }
    __syncthreads();

    const uint32_t Abase = (uint32_t)__cvta_generic_to_shared(A_s);
    const uint32_t laneA = (uint32_t)(((lane & 15) * APW + ((lane >> 4) << 2)) << 2);

    // ---- phase 1: warp-autonomous selection tiles ----
    const int gw = blockIdx.x * 8 + wid;
    for (int widx = gw; widx < WT_TOTAL; widx += NWRP) {
        const int os = widx & 3;
        const int tw = (widx >> 2) & 127;
        const int b  = widx >> 9;
        const int t0 = tw << 6;
        const float* xb = xg + b * CC * LL;
        const uint32_t a0 = Abase + ((uint32_t)(os * 32 * APW) << 2) + laneA;
        const uint32_t a1 = a0 + ((16 * APW) << 2);
        if (tw == 127)
            process_tile<true >(xb, t0, a0, a1, Pw, b, os, lane, r4, q4);
        else
            process_tile<false>(xb, t0, a0, a1, Pw, b, os, lane, r4, q4);
    }

    // ---- grid-wide ticket barrier (all NBLK blocks resident in wave 1) ----
    __threadfence();
    __syncthreads();
    if (tid == 0) {
        atomicAdd(&g_counter, 1u);
        unsigned int v;
        do {
            asm volatile("ld.global.acquire.gpu.u32 %0, [%1];"
                         : "=r"(v) : "l"(&g_counter));
        } while (v < NBLK);
    }
    __syncthreads();

    // ---- phase 2: exact fp32 recompute of selected features ----
    for (int u = gw; u < BB * OO; u += NWRP) {
        ull pk = g_max2[u];
        int t = (int)(unsigned)(pk & 0xffffffffu);
        int b = u >> 7, o = u & (OO - 1);
        float conv = 0.f, wsq = 0.f, xsq = 0.f;
        #pragma unroll
        for (int j = 0; j < 6; ++j) {
            int kl = lane + 32 * j;
            int c = kl >> 6, k = kl & 63;
            float wv = wg[o * KRED + kl];
            float xv = xg[(b * CC + c) * LL + t + k];
            conv = fmaf(wv, xv, conv);
            wsq  = fmaf(wv, wv, wsq);
            xsq  = fmaf(xv, xv, xsq);
        }
        #pragma unroll
        for (int d = 16; d; d >>= 1) {
            conv += __shfl_xor_sync(0xffffffffu, conv, d);
            wsq  += __shfl_xor_sync(0xffffffffu, wsq,  d);
            xsq  += __shfl_xor_sync(0xffffffffu, xsq,  d);
        }
        if (lane == 0) {
            out[u] = -2.0f * (conv - 0.5f * xsq - 0.5f * wsq);
            g_max2[u] = 0ull;              // reset for next graph replay
        }
    }

    // ---- completion ticket: last finisher resets both counters ----
    __threadfence();
    __syncthreads();
    if (tid == 0) {
        if (atomicAdd(&g_done, 1u) == NBLK - 1u) {
            g_counter = 0u;
            __threadfence();
            atomicExch(&g_done, 0u);
        }
    }
}

extern "C" void kernel_launch(void* const* d_in, const int* in_sizes, int n_in,
                              void* d_out, int out_size) {
    const float* x = (const float*)d_in[0];
    const float* w = (const float*)d_in[1];
    float* out = (float*)d_out;

    cudaFuncSetAttribute(shapeconv_fused,
                         cudaFuncAttributeMaxDynamicSharedMemorySize, SMEM_BYTES);
    shapeconv_fused<<<NBLK, 256, SMEM_BYTES>>>(x, w, out);
}

// round 17
// speedup vs baseline: 1.0982x; 1.0982x over previous
#include <cuda_runtime.h>
#include <cuda_fp16.h>
#include <cstdint>

// ShapeConv two-kernel (R14 structure): fp16 mma.sync (f16 accum) argmax
// selection + exact fp32 recompute at selected t.
// Round-17: all 45 B-fragment global loads hoisted to tile start (single
// MLP-45 latency wait per tile instead of 3 serial per-channel waits that
// idled the tensor pipe ~50%); exact kernel at 512 blocks (1 unit/warp).

#define BB 32
#define CC 3
#define LL 8192
#define OO 128
#define KW 64
#define WW (LL - KW + 1)   /* 8129 valid windows */
#define KRED 192
#define APW 100            /* A pitch in 32-bit words (96 data + 4 pad) */
#define NBLK 296
#define NWRP (NBLK * 8)
#define WT_TOTAL (BB * 4 * 128)   /* 16384 warp-tiles: 32o x 64t */

#define A_OFF 0u           /* 128*APW f16x2 words = 51200 B */
#define P_OFF 51200u       /* 8 warps x 128 f32 prefix arrays */
#define SMEM_BYTES 55296

typedef unsigned long long ull;

__device__ ull g_max2[BB * OO];    // (mono(val)<<32 | t), zero-init, reset after read

__device__ __forceinline__ unsigned int f2mono(float f) {
    unsigned int u = __float_as_uint(f);
    return (u & 0x80000000u) ? ~u : (u | 0x80000000u);
}
__device__ __forceinline__ uint32_t pack_h2(float lo, float hi) {
    __half2 h = __floats2half2_rn(lo, hi);
    return *(uint32_t*)&h;
}
__device__ __forceinline__ void mma_f16a(uint32_t* d, const uint32_t* a,
                                         uint32_t b0, uint32_t b1) {
    asm volatile(
        "mma.sync.aligned.m16n8k16.row.col.f16.f16.f16.f16 "
        "{%0,%1}, {%2,%3,%4,%5}, {%6,%7}, {%0,%1};"
        : "+r"(d[0]), "+r"(d[1])
        : "r"(a[0]), "r"(a[1]), "r"(a[2]), "r"(a[3]), "r"(b0), "r"(b1));
}
__device__ __forceinline__ void ldsm_x4(uint32_t* a, uint32_t saddr) {
    asm volatile(
        "ldmatrix.sync.aligned.m8n8.x4.shared.b16 {%0,%1,%2,%3}, [%4];"
        : "=r"(a[0]), "=r"(a[1]), "=r"(a[2]), "=r"(a[3]) : "r"(saddr));
}

// ---------------- one warp-tile: 32 o x 64 t, K=192 ----------------
template <bool EDGE>
__device__ __forceinline__ void process_tile(
    const float* __restrict__ xb, int t0, uint32_t addrA0, uint32_t addrA1,
    float* __restrict__ Pw, int b, int os, int lane, int r4, int q4)
{
    __syncwarp();   // previous tile's Pw reads complete

    // ---- exclusive prefix of squared sums over [t0, t0+128) ----
    {
        int gi = t0 + 4 * lane;
        if (EDGE) gi = min(gi, LL - 4);
        float4 c0 = *(const float4*)(xb + gi);
        float4 c1 = *(const float4*)(xb + LL + gi);
        float4 c2 = *(const float4*)(xb + 2 * LL + gi);
        float s0 = c0.x*c0.x + c1.x*c1.x + c2.x*c2.x;
        float s1 = c0.y*c0.y + c1.y*c1.y + c2.y*c2.y;
        float s2 = c0.z*c0.z + c1.z*c1.z + c2.z*c2.z;
        float s3 = c0.w*c0.w + c1.w*c1.w + c2.w*c2.w;
        float e1 = s0, e2 = s0 + s1, e3 = e2 + s2, tot = e3 + s3;
        float sc = tot;
        #pragma unroll
        for (int d = 1; d < 32; d <<= 1) {
            float t = __shfl_up_sync(0xffffffffu, sc, d);
            if (lane >= d) sc += t;
        }
        float base = sc - tot;
        *(float4*)(Pw + 4*lane) = make_float4(base, base+e1, base+e2, base+e3);
    }
    __syncwarp();

    // ---- hoist ALL B-fragment loads: 45 LDG issued back-to-back (MLP=45),
    //      ONE latency wait per tile; mainloop becomes pure LDS+HMMA ----
    uint32_t bb[CC][15];
    const int off = t0 + r4 + 2 * q4;
    #pragma unroll
    for (int c = 0; c < CC; ++c) {
        const float* xc = xb + c * LL;
        #pragma unroll
        for (int u = 0; u < 15; ++u) {
            float v0, v1;
            if (EDGE) {
                int p = off + 8 * u;
                v0 = xc[min(p, LL - 1)];
                v1 = xc[min(p + 1, LL - 1)];
            } else {
                v0 = xc[off + 8 * u];
                v1 = xc[off + 8 * u + 1];
            }
            bb[c][u] = pack_h2(v0, v1);
        }
    }

    // ---- fp16 MMA mainloop (f16 accum) ----
    uint32_t acc[2][8][2];
    #pragma unroll
    for (int mi = 0; mi < 2; ++mi)
        #pragma unroll
        for (int nf = 0; nf < 8; ++nf) { acc[mi][nf][0] = 0u; acc[mi][nf][1] = 0u; }

    #pragma unroll
    for (int c = 0; c < CC; ++c) {
        #pragma unroll
        for (int j = 0; j < 4; ++j) {
            const uint32_t cb = (uint32_t)(c * 32 + j * 8) << 2;
            uint32_t a[2][4];
            ldsm_x4(a[0], addrA0 + cb);
            ldsm_x4(a[1], addrA1 + cb);
            #pragma unroll
            for (int nf = 0; nf < 8; ++nf) {
                uint32_t b0 = bb[c][2 * j + nf], b1 = bb[c][2 * j + nf + 1];
                mma_f16a(acc[0][nf], a[0], b0, b1);
                mma_f16a(acc[1][nf], a[1], b0, b1);
            }
        }
    }

    // ---- epilogue: (val, t) argmax per row with exact-win subtraction ----
    float mv[2][2];  int mx[2][2];
    #pragma unroll
    for (int mi = 0; mi < 2; ++mi)
        #pragma unroll
        for (int h = 0; h < 2; ++h) { mv[mi][h] = __int_as_float(0xff800000); mx[mi][h] = t0; }

    #pragma unroll
    for (int nf = 0; nf < 8; ++nf) {
        const int n0 = nf * 8 + 2 * q4;
        float w0 = 0.5f * (Pw[n0 + 64] - Pw[n0]);
        float w1 = 0.5f * (Pw[n0 + 65] - Pw[n0 + 1]);
        if (EDGE) {
            if (t0 + n0 >= WW)     w0 = __int_as_float(0x7f800000);
            if (t0 + n0 + 1 >= WW) w1 = __int_as_float(0x7f800000);
        }
        const int ti0 = t0 + n0, ti1 = t0 + n0 + 1;
        #pragma unroll
        for (int mi = 0; mi < 2; ++mi) {
            float2 lo = __half22float2(*(__half2*)&acc[mi][nf][0]);
            float2 hi = __half22float2(*(__half2*)&acc[mi][nf][1]);
            float f0 = lo.x - w0, f1 = lo.y - w1;
            float f2 = hi.x - w0, f3 = hi.y - w1;
            if (f0 > mv[mi][0]) { mv[mi][0] = f0; mx[mi][0] = ti0; }
            if (f1 > mv[mi][0]) { mv[mi][0] = f1; mx[mi][0] = ti1; }
            if (f2 > mv[mi][1]) { mv[mi][1] = f2; mx[mi][1] = ti0; }
            if (f3 > mv[mi][1]) { mv[mi][1] = f3; mx[mi][1] = ti1; }
        }
    }
    #pragma unroll
    for (int mi = 0; mi < 2; ++mi)
        #pragma unroll
        for (int h = 0; h < 2; ++h) {
            #pragma unroll
            for (int d = 1; d <= 2; d <<= 1) {
                float ov = __shfl_xor_sync(0xffffffffu, mv[mi][h], d);
                int   oi = __shfl_xor_sync(0xffffffffu, mx[mi][h], d);
                if (ov > mv[mi][h]) { mv[mi][h] = ov; mx[mi][h] = oi; }
            }
        }
    if (q4 == 0) {
        #pragma unroll
        for (int mi = 0; mi < 2; ++mi)
            #pragma unroll
            for (int h = 0; h < 2; ++h) {
                int row = os * 32 + mi * 16 + h * 8 + r4;
                ull pk = ((ull)f2mono(mv[mi][h]) << 32) | (unsigned)mx[mi][h];
                atomicMax(&g_max2[b * OO + row], pk);
            }
    }
}

extern "C" __global__ void __launch_bounds__(256, 2)
shapeconv_sel(const float* __restrict__ xg, const float* __restrict__ wg) {
    extern __shared__ char smem[];
    uint32_t* A_s = (uint32_t*)(smem + A_OFF);   // [128][APW] f16x2

    const int tid  = threadIdx.x;
    const int wid  = tid >> 5;
    const int lane = tid & 31;
    const int r4   = lane >> 2;
    const int q4   = lane & 3;

    float* Pw = (float*)(smem + P_OFF) + wid * 128;

    // ---- A staging: warp w owns o-rows [16w,16w+16); coalesced float2 -> f16x2
    {
        const int o0w = wid * 16;
        #pragma unroll 4
        for (int oi = 0; oi < 16; ++oi) {
            const int o = o0w + oi;
            const float2* wp = (const float2*)(wg + o * KRED);
            float2 v0 = wp[lane], v1 = wp[lane + 32], v2 = wp[lane + 64];
            uint32_t* ap = A_s + o * APW;
            ap[lane]      = pack_h2(v0.x, v0.y);
            ap[lane + 32] = pack_h2(v1.x, v1.y);
            ap[lane + 64] = pack_h2(v2.x, v2.y);
        }
    }
    __syncthreads();

    const uint32_t Abase = (uint32_t)__cvta_generic_to_shared(A_s);
    const uint32_t laneA = (uint32_t)(((lane & 15) * APW + ((lane >> 4) << 2)) << 2);

    // ---- warp-autonomous tiles: os fastest (x window reuse across o-slices)
    const int gw = blockIdx.x * 8 + wid;
    for (int widx = gw; widx < WT_TOTAL; widx += NWRP) {
        const int os = widx & 3;
        const int tw = (widx >> 2) & 127;
        const int b  = widx >> 9;
        const int t0 = tw << 6;
        const float* xb = xg + b * CC * LL;
        const uint32_t a0 = Abase + ((uint32_t)(os * 32 * APW) << 2) + laneA;
        const uint32_t a1 = a0 + ((16 * APW) << 2);
        if (tw == 127)
            process_tile<true >(xb, t0, a0, a1, Pw, b, os, lane, r4, q4);
        else
            process_tile<false>(xb, t0, a0, a1, Pw, b, os, lane, r4, q4);
    }
}

// ---- exact fp32 recompute of the selected feature per (b,o) + reset ----
extern "C" __global__ void __launch_bounds__(256)
shapeconv_exact(const float* __restrict__ xg, const float* __restrict__ wg,
                float* __restrict__ out) {
    const int wid  = threadIdx.x >> 5;
    const int lane = threadIdx.x & 31;
    const int u    = blockIdx.x * 8 + wid;       // one (b,o) per warp
    if (u >= BB * OO) return;
    ull pk = g_max2[u];
    int t = (int)(unsigned)(pk & 0xffffffffu);
    int b = u >> 7, o = u & (OO - 1);
    float conv = 0.f, wsq = 0.f, xsq = 0.f;
    #pragma unroll
    for (int j = 0; j < 6; ++j) {
        int kl = lane + 32 * j;
        int c = kl >> 6, k = kl & 63;
        float wv = wg[o * KRED + kl];
        float xv = xg[(b * CC + c) * LL + t + k];
        conv = fmaf(wv, xv, conv);
        wsq  = fmaf(wv, wv, wsq);
        xsq  = fmaf(xv, xv, xsq);
    }
    #pragma unroll
    for (int d = 16; d; d >>= 1) {
        conv += __shfl_xor_sync(0xffffffffu, conv, d);
        wsq  += __shfl_xor_sync(0xffffffffu, wsq,  d);
        xsq  += __shfl_xor_sync(0xffffffffu, xsq,  d);
    }
    if (lane == 0) {
        out[u] = -2.0f * (conv - 0.5f * xsq - 0.5f * wsq);
        g_max2[u] = 0ull;                  // reset for next graph replay
    }
}

extern "C" void kernel_launch(void* const* d_in, const int* in_sizes, int n_in,
                              void* d_out, int out_size) {
    const float* x = (const float*)d_in[0];
    const float* w = (const float*)d_in[1];
    float* out = (float*)d_out;

    cudaFuncSetAttribute(shapeconv_sel,
                         cudaFuncAttributeMaxDynamicSharedMemorySize, SMEM_BYTES);
    shapeconv_sel<<<NBLK, 256, SMEM_BYTES>>>(x, w);
    shapeconv_exact<<<512, 256>>>(x, w, out);
}